// round 8
// baseline (speedup 1.0000x reference)
#include <cuda_runtime.h>

#define NB     256
#define NPIX   (1024*1024)
#define NBATCH 16
#define G      8                  // images per group (100 MB staged in L2)
#define NGROUP (NBATCH / G)
#define TPB    256
#define IT_H   4                  // hist: float4 per thread (16 px/thread)
#define IT_M   2                  // map : float4 per thread
#define BLKX_H (NPIX / 4 / (TPB * IT_H))   // 256 blocks per image
#define BLKX_M (NPIX / 4 / (TPB * IT_M))   // 512 blocks per image
#define HIST_SMEM (NB * TPB)      // 64 KB byte counters

// Scratch (no allocations). g_histo is zero at load and re-zeroed by
// lut_kernel after consumption, so every graph replay sees zeros.
__device__ int   g_histo[NBATCH][NB];
__device__ float g_lut[NBATCH][NB];
__device__ float g_step[NBATCH];

__device__ __forceinline__ float clip01(float x) {
    return fminf(fmaxf(x, 0.0f), 1.0f);
}

// Pass 1: per-image histogram of Y bins. NO atomics in the hot loop:
// per-(bin,thread) u8 counters in 64 KB smem; each thread owns its byte.
// Merge via dp4a, one global atomic per bin per block.
__global__ void hist_kernel(const float* __restrict__ img, int img_base) {
    extern __shared__ unsigned char sh8[];        // [NB][TPB] bytes, swizzled
    unsigned int* sh32 = (unsigned int*)sh8;

    for (int i = threadIdx.x; i < NB * TPB / 4; i += TPB) sh32[i] = 0;
    __syncthreads();

    const int b = img_base + blockIdx.y;
    const size_t base = (size_t)b * 3 * NPIX;
    const float4* __restrict__ R  = (const float4*)(img + base);
    const float4* __restrict__ Gc = (const float4*)(img + base + NPIX);
    const float4* __restrict__ B  = (const float4*)(img + base + 2 * NPIX);

    const int tile = blockIdx.x * (TPB * IT_H);
    const int t    = threadIdx.x;
    const float scale = (float)(256.0 / 255.0);   // NUM_BINS / 255.0 in f32

    // Front-batched loads: 12 LDG.128 in flight per thread (MLP for 24 warps).
    float4 r4[IT_H], g4[IT_H], b4[IT_H];
    #pragma unroll
    for (int k = 0; k < IT_H; k++) {
        int i = tile + k * TPB + t;
        r4[k] = R[i]; g4[k] = Gc[i]; b4[k] = B[i];
    }

    #pragma unroll
    for (int k = 0; k < IT_H; k++) {
        #pragma unroll
        for (int c = 0; c < 4; c++) {
            float r  = clip01(((const float*)&r4[k])[c]);
            float g  = clip01(((const float*)&g4[k])[c]);
            float bb = clip01(((const float*)&b4[k])[c]);
            float y = 0.299f * r + 0.587f * g + 0.114f * bb;
            int bin = (int)floorf(y * 255.0f * scale);
            bin = min(max(bin, 0), NB - 1);
            // Unique byte slot per (bin, thread); swizzled column spreads banks.
            int idx = bin * TPB + ((t + 4 * bin) & (TPB - 1));
            sh8[idx] = (unsigned char)(sh8[idx] + 1);
        }
    }
    __syncthreads();

    // Merge: thread t sums row t (64 words) with dp4a, lane-staggered.
    const unsigned int* row = sh32 + t * (TPB / 4);
    unsigned int acc = 0u;
    #pragma unroll
    for (int w = 0; w < TPB / 4; w++) {
        acc = __dp4a(row[(w + t) & (TPB / 4 - 1)], 0x01010101u, acc);
    }
    if (acc) atomicAdd(&g_histo[b][t], (int)acc);
}

// LUT: one block per image; resets the histogram for the next graph replay.
__global__ void lut_kernel(int img_base) {
    const int b = img_base + blockIdx.x;
    const int t = threadIdx.x;

    __shared__ float h[NB];
    __shared__ float s[NB];
    __shared__ int   lastIdx;

    float hv = (float)g_histo[b][t];
    g_histo[b][t] = 0;                    // reset for next replay
    h[t] = hv;
    s[t] = hv;
    if (t == 0) lastIdx = 0;
    __syncthreads();

    // Inclusive Hillis-Steele scan (fp32 exact: counts < 2^24).
    for (int off = 1; off < NB; off <<= 1) {
        float add = (t >= off) ? s[t - off] : 0.0f;
        __syncthreads();
        s[t] += add;
        __syncthreads();
    }

    if (hv > 0.0f) atomicMax(&lastIdx, t);
    __syncthreads();

    float total    = s[NB - 1];
    float last_val = h[lastIdx];
    float step     = floorf(__fdiv_rn(total - last_val, 255.0f));
    float safe     = fmaxf(step, 1.0f);
    float half     = floorf(__fdiv_rn(step, 2.0f));

    float lv;
    if (t == 0) {
        lv = 0.0f;
    } else {
        lv = floorf(__fdiv_rn(s[t - 1] + half, safe));
        lv = fminf(fmaxf(lv, 0.0f), 255.0f);
    }
    g_lut[b][t] = lv;
    if (t == 0) g_step[b] = step;
}

// Pass 2: map Y through LUT, recombine with U/V, convert back to RGB.
// Reads should hit L2 (staged by hist); __ldcs demotes after last touch.
// __stcs: output lines evict-first so they don't displace staged input.
__global__ void map_kernel(const float* __restrict__ img, float* __restrict__ out,
                           int img_base) {
    __shared__ float lut[NB];
    __shared__ float stepv;

    const int b = img_base + blockIdx.y;
    for (int i = threadIdx.x; i < NB; i += TPB) lut[i] = g_lut[b][i];
    if (threadIdx.x == 0) stepv = g_step[b];
    __syncthreads();

    const bool identity = (stepv == 0.0f);

    const size_t base = (size_t)b * 3 * NPIX;
    const float4* __restrict__ R  = (const float4*)(img + base);
    const float4* __restrict__ Gc = (const float4*)(img + base + NPIX);
    const float4* __restrict__ B  = (const float4*)(img + base + 2 * NPIX);
    float4* __restrict__ Ro = (float4*)(out + base);
    float4* __restrict__ Go = (float4*)(out + base + NPIX);
    float4* __restrict__ Bo = (float4*)(out + base + 2 * NPIX);

    const int tile = blockIdx.x * (TPB * IT_M);
    const float inv255 = 1.0f / 255.0f;

    #pragma unroll
    for (int k = 0; k < IT_M; k++) {
        int i = tile + k * TPB + threadIdx.x;
        float4 r4 = __ldcs(R + i);
        float4 g4 = __ldcs(Gc + i);
        float4 b4 = __ldcs(B + i);
        float4 ro, go, bo;
        #pragma unroll
        for (int c = 0; c < 4; c++) {
            float r  = clip01(((const float*)&r4)[c]);
            float g  = clip01(((const float*)&g4)[c]);
            float bb = clip01(((const float*)&b4)[c]);

            float y = 0.299f * r + 0.587f * g + 0.114f * bb;
            float u = -0.147f * r - 0.289f * g + 0.436f * bb;
            float v = 0.615f * r - 0.515f * g - 0.100f * bb;

            float t = y * 255.0f;
            int gi = min(max((int)t, 0), NB - 1);
            float outv = identity ? t : lut[gi];
            float ye = outv * inv255;

            ((float*)&ro)[c] = ye + 1.14f * v;
            ((float*)&go)[c] = ye - 0.396f * u - 0.581f * v;
            ((float*)&bo)[c] = ye + 2.029f * u;
        }
        __stcs(Ro + i, ro);
        __stcs(Go + i, go);
        __stcs(Bo + i, bo);
    }
}

static bool g_inited = false;

extern "C" void kernel_launch(void* const* d_in, const int* in_sizes, int n_in,
                              void* d_out, int out_size) {
    const float* img = (const float*)d_in[0];
    float*       out = (float*)d_out;

    if (!g_inited) {
        cudaFuncSetAttribute(hist_kernel,
                             cudaFuncAttributeMaxDynamicSharedMemorySize,
                             HIST_SMEM);
        g_inited = true;
    }

    // Two 100 MB groups, strictly sequential: hist stages the group in L2,
    // map consumes it from L2.
    for (int g = 0; g < NGROUP; g++) {
        dim3 gh(BLKX_H, G);
        dim3 gm(BLKX_M, G);
        hist_kernel<<<gh, TPB, HIST_SMEM>>>(img, g * G);
        lut_kernel<<<G, NB>>>(g * G);
        map_kernel<<<gm, TPB>>>(img, out, g * G);
    }
}

// round 9
// speedup vs baseline: 1.1866x; 1.1866x over previous
#include <cuda_runtime.h>

#define NB     256
#define NPIX   (1024*1024)
#define NBATCH 16
#define G      8                  // images per group (100 MB staged in L2)
#define NGROUP (NBATCH / G)
#define IT     2                  // float4 items per thread
#define TPB    256
#define BLKX   (NPIX / 4 / (TPB * IT))   // 512 blocks per image
#define NSUB   8                  // one sub-histogram per warp

// Scratch (no allocations). g_histo is zero at load and re-zeroed by
// lut_kernel after consumption, so every graph replay sees zeros.
__device__ int   g_histo[NBATCH][NB];
__device__ float g_lut[NBATCH][NB];
__device__ float g_step[NBATCH];

__device__ __forceinline__ float clip01(float x) {
    return fminf(fmaxf(x, 0.0f), 1.0f);
}

// Pass 1: per-image histogram of Y bins. Per-warp sub-histograms kill
// inter-warp atomic conflicts. (Best measured config: 23.1 us / 8 images.)
__global__ void hist_kernel(const float* __restrict__ img, int img_base) {
    __shared__ int sub[NSUB * NB];    // 8 KB
    for (int i = threadIdx.x; i < NSUB * NB; i += TPB) sub[i] = 0;
    __syncthreads();

    const int b = img_base + blockIdx.y;
    const size_t base = (size_t)b * 3 * NPIX;
    const float4* __restrict__ R  = (const float4*)(img + base);
    const float4* __restrict__ Gc = (const float4*)(img + base + NPIX);
    const float4* __restrict__ B  = (const float4*)(img + base + 2 * NPIX);

    const int tile = blockIdx.x * (TPB * IT);
    const float scale = (float)(256.0 / 255.0);   // NUM_BINS / 255.0 in f32
    int* mysub = &sub[(threadIdx.x >> 5) * NB];   // private per warp

    #pragma unroll
    for (int k = 0; k < IT; k++) {
        int i = tile + k * TPB + threadIdx.x;
        float4 r4 = R[i], g4 = Gc[i], b4 = B[i];
        #pragma unroll
        for (int c = 0; c < 4; c++) {
            float r  = clip01(((const float*)&r4)[c]);
            float g  = clip01(((const float*)&g4)[c]);
            float bb = clip01(((const float*)&b4)[c]);
            float y = 0.299f * r + 0.587f * g + 0.114f * bb;
            int bin = (int)floorf(y * 255.0f * scale);
            bin = min(max(bin, 0), NB - 1);
            atomicAdd(&mysub[bin], 1);
        }
    }
    __syncthreads();

    // Merge 8 sub-histograms; one global atomic per bin per block (TPB == NB).
    int t = threadIdx.x;
    int tot = 0;
    #pragma unroll
    for (int w = 0; w < NSUB; w++) tot += sub[w * NB + t];
    if (tot) atomicAdd(&g_histo[b][t], tot);
}

// LUT: one block per image; resets the histogram for the next graph replay.
__global__ void lut_kernel(int img_base) {
    const int b = img_base + blockIdx.x;
    const int t = threadIdx.x;

    __shared__ float h[NB];
    __shared__ float s[NB];
    __shared__ int   lastIdx;

    float hv = (float)g_histo[b][t];
    g_histo[b][t] = 0;                    // reset for next replay
    h[t] = hv;
    s[t] = hv;
    if (t == 0) lastIdx = 0;
    __syncthreads();

    // Inclusive Hillis-Steele scan (fp32 exact: counts < 2^24).
    for (int off = 1; off < NB; off <<= 1) {
        float add = (t >= off) ? s[t - off] : 0.0f;
        __syncthreads();
        s[t] += add;
        __syncthreads();
    }

    if (hv > 0.0f) atomicMax(&lastIdx, t);
    __syncthreads();

    float total    = s[NB - 1];
    float last_val = h[lastIdx];
    float step     = floorf(__fdiv_rn(total - last_val, 255.0f));
    float safe     = fmaxf(step, 1.0f);
    float half     = floorf(__fdiv_rn(step, 2.0f));

    float lv;
    if (t == 0) {
        lv = 0.0f;
    } else {
        lv = floorf(__fdiv_rn(s[t - 1] + half, safe));
        lv = fminf(fmaxf(lv, 0.0f), 255.0f);
    }
    g_lut[b][t] = lv;
    if (t == 0) g_step[b] = step;
}

// Pass 2: map Y through LUT, recombine with U/V, convert back to RGB.
// Reads should hit L2 (staged by hist); __ldcs demotes after the last touch.
// __stcs: output lines evict-first so they never displace staged input.
__global__ void map_kernel(const float* __restrict__ img, float* __restrict__ out,
                           int img_base) {
    __shared__ float lut[NB];
    __shared__ float stepv;

    const int b = img_base + blockIdx.y;
    for (int i = threadIdx.x; i < NB; i += TPB) lut[i] = g_lut[b][i];
    if (threadIdx.x == 0) stepv = g_step[b];
    __syncthreads();

    const bool identity = (stepv == 0.0f);

    const size_t base = (size_t)b * 3 * NPIX;
    const float4* __restrict__ R  = (const float4*)(img + base);
    const float4* __restrict__ Gc = (const float4*)(img + base + NPIX);
    const float4* __restrict__ B  = (const float4*)(img + base + 2 * NPIX);
    float4* __restrict__ Ro = (float4*)(out + base);
    float4* __restrict__ Go = (float4*)(out + base + NPIX);
    float4* __restrict__ Bo = (float4*)(out + base + 2 * NPIX);

    const int tile = blockIdx.x * (TPB * IT);
    const float inv255 = 1.0f / 255.0f;

    #pragma unroll
    for (int k = 0; k < IT; k++) {
        int i = tile + k * TPB + threadIdx.x;
        float4 r4 = __ldcs(R + i);
        float4 g4 = __ldcs(Gc + i);
        float4 b4 = __ldcs(B + i);
        float4 ro, go, bo;
        #pragma unroll
        for (int c = 0; c < 4; c++) {
            float r  = clip01(((const float*)&r4)[c]);
            float g  = clip01(((const float*)&g4)[c]);
            float bb = clip01(((const float*)&b4)[c]);

            float y = 0.299f * r + 0.587f * g + 0.114f * bb;
            float u = -0.147f * r - 0.289f * g + 0.436f * bb;
            float v = 0.615f * r - 0.515f * g - 0.100f * bb;

            float t = y * 255.0f;
            int gi = min(max((int)t, 0), NB - 1);
            float outv = identity ? t : lut[gi];
            float ye = outv * inv255;

            ((float*)&ro)[c] = ye + 1.14f * v;
            ((float*)&go)[c] = ye - 0.396f * u - 0.581f * v;
            ((float*)&bo)[c] = ye + 2.029f * u;
        }
        __stcs(Ro + i, ro);
        __stcs(Go + i, go);
        __stcs(Bo + i, bo);
    }
}

// Lazy one-time resources (created on the correctness call, outside capture).
static bool         g_inited = false;
static cudaStream_t g_s1;
static cudaEvent_t  g_evLut[NGROUP];
static cudaEvent_t  g_evDone;

extern "C" void kernel_launch(void* const* d_in, const int* in_sizes, int n_in,
                              void* d_out, int out_size) {
    const float* img = (const float*)d_in[0];
    float*       out = (float*)d_out;

    if (!g_inited) {
        cudaStreamCreateWithFlags(&g_s1, cudaStreamNonBlocking);
        for (int g = 0; g < NGROUP; g++)
            cudaEventCreateWithFlags(&g_evLut[g], cudaEventDisableTiming);
        cudaEventCreateWithFlags(&g_evDone, cudaEventDisableTiming);
        g_inited = true;
    }

    // Two 100 MB groups. Single overlap window: map(0) on s1 runs while
    // hist(1) runs on the origin stream. Both are full-machine-scale
    // kernels, so concurrency combines their DRAM phases instead of
    // serializing under-utilized ones.
    for (int g = 0; g < NGROUP; g++) {
        dim3 grid(BLKX, G);
        hist_kernel<<<grid, TPB>>>(img, g * G);
        lut_kernel<<<G, NB>>>(g * G);
        cudaEventRecord(g_evLut[g], 0);
        cudaStreamWaitEvent(g_s1, g_evLut[g], 0);
        map_kernel<<<grid, TPB, 0, g_s1>>>(img, out, g * G);
    }
    cudaEventRecord(g_evDone, g_s1);
    cudaStreamWaitEvent(0, g_evDone, 0);
}